// round 1
// baseline (speedup 1.0000x reference)
#include <cuda_runtime.h>
#include <cstdint>

// ============================================================================
// RNN_35244501631277 — GB300 persistent-grid recurrence
//
// Key algebraic transform: OUT==1 means the readout is linear before sigmoid,
// so we project each table row once (119x2 dots) instead of gathering 16384
// rows of 2048 floats. The expensive part is the 476-phase sequential matvec
// recurrence, run in ONE persistent kernel with a distributed flag barrier.
// ============================================================================

#define H          2048
#define STEPS      119
#define NB         16384
#define CPC        128        // CTAs per chain
#define NCTAS      256        // 2 chains
#define NTHREADS   1024
#define COLS       16         // output columns per CTA

// Device-global scratch (no allocation allowed in kernel_launch)
__device__ float g_p[2][H];             // current state per chain
__device__ float g_t[2][H];             // intermediate h per chain
__device__ float g_tab[2][STEPS][H];    // state tables
__device__ float g_proj[2][STEPS];      // projected tables (dot with rW)
__device__ int   g_flags[2][CPC];       // distributed barrier flags

__device__ __forceinline__ float silu(float x) {
    return x / (1.0f + __expf(-x));
}

// Distributed grid barrier for one chain's 128 CTAs.
// Writer side must have done: stores + __threadfence() before calling.
__device__ __forceinline__ void gbar(int chain, int lc, int tid, int epoch) {
    __syncthreads();
    if (tid == 0) {
        __threadfence();
        atomicExch(&g_flags[chain][lc], epoch);
    }
    volatile int* vf = g_flags[chain];
    for (;;) {
        int ok = 1;
        if (tid < CPC) ok = (vf[tid] >= epoch);
        if (__syncthreads_and(ok)) break;
        __nanosleep(128);
    }
    __threadfence();
}

// Matvec over this CTA's 16 columns: y[c0..c0+15] = vec(2048) . W[:, c0..c0+15]
// Wv already offset to column group c0. Returns float4 valid for tid<4
// (tid t holds columns c0+4t .. c0+4t+3).
__device__ __forceinline__ float4 matvec16(const float4* __restrict__ Wv,
                                           const float* __restrict__ vec,
                                           float* ps, float4 (*red)[4], int tid) {
    // Stage full input vector into smem (L2 reads, bypass L1 for freshness)
    ps[tid]        = __ldcg(vec + tid);
    ps[tid + 1024] = __ldcg(vec + tid + 1024);
    __syncthreads();

    const int it = tid >> 2;      // 0..255 : row-partial index
    const int jv = tid & 3;       // 0..3   : float4 column group
    float4 acc = make_float4(0.f, 0.f, 0.f, 0.f);
    const float4* wp = Wv + (size_t)it * (H / 4) + jv;
    #pragma unroll 4
    for (int k = 0; k < 8; ++k) {
        float4 w = __ldcg(wp);
        float pv = ps[it + (k << 8)];
        acc.x += w.x * pv; acc.y += w.y * pv;
        acc.z += w.z * pv; acc.w += w.w * pv;
        wp += 256 * (H / 4);
    }
    red[it][jv] = acc;
    __syncthreads();
    #pragma unroll
    for (int s = 128; s > 0; s >>= 1) {
        if (it < s) {
            float4 a = red[it][jv];
            float4 b = red[it + s][jv];
            a.x += b.x; a.y += b.y; a.z += b.z; a.w += b.w;
            red[it][jv] = a;
        }
        __syncthreads();
    }
    return red[0][jv];
}

extern "C" __global__ void init_flags_kernel() {
    int t = threadIdx.x;
    if (t < NCTAS) ((int*)g_flags)[t] = 0;
}

extern "C" __global__ void __launch_bounds__(NTHREADS, 2)
rnn_kernel(const float* __restrict__ pemb, const float* __restrict__ nemb,
           const float* __restrict__ pW1, const float* __restrict__ pb1,
           const float* __restrict__ pW2, const float* __restrict__ pb2,
           const float* __restrict__ nW1, const float* __restrict__ nb1,
           const float* __restrict__ nW2, const float* __restrict__ nb2,
           const float* __restrict__ rW) {
    __shared__ float  ps[H];          // 8 KB
    __shared__ float4 red[256][4];    // 16 KB

    const int tid   = threadIdx.x;
    const int cta   = blockIdx.x;
    const int chain = cta >> 7;           // 0 = proton, 1 = neutron
    const int lc    = cta & (CPC - 1);    // CTA index within chain
    const int c0    = lc * COLS;          // first owned output column

    const float* W1  = chain ? nW1  : pW1;
    const float* W2  = chain ? nW2  : pW2;
    const float* B1  = chain ? nb1  : pb1;
    const float* B2  = chain ? nb2  : pb2;
    const float* EMB = chain ? nemb : pemb;

    // Prologue: p = emb (each CTA seeds its own 16-column slice)
    if (tid < 4) {
        float4 e = __ldcg((const float4*)(EMB + c0) + tid);
        *((float4*)(&g_p[chain][c0]) + tid) = e;
        __threadfence();
    }
    int epoch = 1;
    gbar(chain, lc, tid, epoch);

    for (int s = 0; s < STEPS; ++s) {
        #pragma unroll
        for (int d = 0; d < 2; ++d) {
            // ---- phase A: t = silu(p @ W1[d] + b1[d]) ----
            {
                const float4* Wv = (const float4*)(W1 + (size_t)d * H * H) + (c0 >> 2);
                float4 a = matvec16(Wv, g_p[chain], ps, red, tid);
                if (tid < 4) {
                    float4 b = __ldcg((const float4*)(B1 + d * H + c0) + tid);
                    float4 y;
                    y.x = silu(a.x + b.x); y.y = silu(a.y + b.y);
                    y.z = silu(a.z + b.z); y.w = silu(a.w + b.w);
                    *((float4*)(&g_t[chain][c0]) + tid) = y;
                    __threadfence();
                }
                gbar(chain, lc, tid, ++epoch);
            }
            // ---- phase B: p = p + silu(t @ W2[d] + b2[d]) ----
            {
                const float4* Wv = (const float4*)(W2 + (size_t)d * H * H) + (c0 >> 2);
                float4 a = matvec16(Wv, g_t[chain], ps, red, tid);
                if (tid < 4) {
                    float4 b  = __ldcg((const float4*)(B2 + d * H + c0) + tid);
                    float4 po = __ldcg((const float4*)(&g_p[chain][c0]) + tid);
                    float4 y;
                    y.x = po.x + silu(a.x + b.x); y.y = po.y + silu(a.y + b.y);
                    y.z = po.z + silu(a.z + b.z); y.w = po.w + silu(a.w + b.w);
                    *((float4*)(&g_p[chain][c0]) + tid) = y;
                    if (d == 1)
                        *((float4*)(&g_tab[chain][s][c0]) + tid) = y;
                    __threadfence();
                }
                gbar(chain, lc, tid, ++epoch);
            }
        }
    }

    // Epilogue: project table rows onto readout weights.
    // CTA lc (< 119) handles row lc of its chain. rW is (2H, 1) row-major.
    if (lc < STEPS) {
        const float* row = g_tab[chain][lc];
        const float* rw  = rW + chain * H;
        float ssum = __ldcg(row + tid)        * __ldcg(rw + tid)
                   + __ldcg(row + tid + 1024) * __ldcg(rw + tid + 1024);
        float* redf = (float*)red;
        redf[tid] = ssum;
        __syncthreads();
        #pragma unroll
        for (int sft = 512; sft > 0; sft >>= 1) {
            if (tid < sft) redf[tid] += redf[tid + sft];
            __syncthreads();
        }
        if (tid == 0) g_proj[chain][lc] = redf[0];
    }
}

extern "C" __global__ void gather_kernel(const int* __restrict__ x,
                                         const float* __restrict__ rb,
                                         float* __restrict__ out) {
    int b = blockIdx.x * blockDim.x + threadIdx.x;
    if (b < NB) {
        int xp = x[2 * b];
        int xn = x[2 * b + 1];
        float z = g_proj[0][xp] + g_proj[1][xn] + rb[0];
        out[b] = 1.0f / (1.0f + __expf(-z));
    }
}

extern "C" void kernel_launch(void* const* d_in, const int* in_sizes, int n_in,
                              void* d_out, int out_size) {
    (void)in_sizes; (void)n_in; (void)out_size;
    const int*   x    = (const int*)d_in[0];
    const float* pemb = (const float*)d_in[1];
    const float* nemb = (const float*)d_in[2];
    const float* pW1  = (const float*)d_in[3];
    const float* pb1  = (const float*)d_in[4];
    const float* pW2  = (const float*)d_in[5];
    const float* pb2  = (const float*)d_in[6];
    const float* nW1  = (const float*)d_in[7];
    const float* nb1  = (const float*)d_in[8];
    const float* nW2  = (const float*)d_in[9];
    const float* nb2  = (const float*)d_in[10];
    const float* rW   = (const float*)d_in[11];
    const float* rb   = (const float*)d_in[12];
    float* out = (float*)d_out;

    init_flags_kernel<<<1, 256>>>();
    rnn_kernel<<<NCTAS, NTHREADS>>>(pemb, nemb, pW1, pb1, pW2, pb2,
                                    nW1, nb1, nW2, nb2, rW);
    gather_kernel<<<(NB + 255) / 256, 256>>>(x, rb, out);
}

// round 2
// speedup vs baseline: 1.8194x; 1.8194x over previous
#include <cuda_runtime.h>
#include <cuda_fp16.h>
#include <cstdint>

// ============================================================================
// RNN_35244501631277 — GB300 persistent recurrence, round 2
//
// R1 lesson: per-phase cost was ~10.8us = ~4.8us DRAM + ~6us barrier/latency.
// This round:
//   (a) weights converted to fp16 in a CTA-sliced contiguous layout (67MB,
//       fits L2) -> weight stream comes from L2, not DRAM
//   (b) next-phase weights prefetched into registers BEFORE the grid barrier
//   (c) cheaper barrier: divergent per-flag spin + single __syncthreads
// States/bias/readout stay fp32; only weights are fp16.
// ============================================================================

#define H          2048
#define STEPS      119
#define NB         16384
#define CPC        128        // CTAs per chain
#define NCTAS      256
#define NTHREADS   1024
#define COLS       16
#define NPHASES    476        // STEPS * DEPTH * 2

__device__ __half g_wh[8][H * H];       // [chain*4 + d*2 + layer], CTA-sliced
__device__ float  g_p[2][H];
__device__ float  g_t[2][H];
__device__ float  g_tab[2][STEPS][H];
__device__ float  g_proj[2][STEPS];
__device__ int    g_flags[2][CPC];

__device__ __forceinline__ float silu(float x) {
    return x / (1.0f + __expf(-x));
}

// ---------------------------------------------------------------------------
// fp32 -> fp16 conversion into CTA-sliced layout:
//   dst[m][lc*H*16 + row*16 + c]  holds  W_m[row][lc*16 + c]
// One thread per (matrix, row, 8-col group). __ldcs keeps fp32 out of L2.
// ---------------------------------------------------------------------------
extern "C" __global__ void convert_kernel(const float* __restrict__ pW1,
                                          const float* __restrict__ pW2,
                                          const float* __restrict__ nW1,
                                          const float* __restrict__ nW2) {
    const int idx = blockIdx.x * blockDim.x + threadIdx.x;   // 8*2048*256
    const int m   = idx >> 19;            // / (2048*256)
    const int rem = idx & ((1 << 19) - 1);
    const int row = rem >> 8;
    const int g   = rem & 255;            // 8-col group

    const int chain = m >> 2, d = (m >> 1) & 1, l = m & 1;
    const float* src = (l ? (chain ? nW2 : pW2) : (chain ? nW1 : pW1))
                       + (size_t)d * H * H + (size_t)row * H + g * 8;

    float4 f0 = __ldcs((const float4*)src);
    float4 f1 = __ldcs((const float4*)src + 1);

    __half h[8];
    h[0] = __float2half_rn(f0.x); h[1] = __float2half_rn(f0.y);
    h[2] = __float2half_rn(f0.z); h[3] = __float2half_rn(f0.w);
    h[4] = __float2half_rn(f1.x); h[5] = __float2half_rn(f1.y);
    h[6] = __float2half_rn(f1.z); h[7] = __float2half_rn(f1.w);

    const int lc = g >> 1;                // col0/16
    const int co = (g & 1) * 8;
    __half* dst = &g_wh[m][(size_t)lc * H * 16 + row * 16 + co];
    *(uint4*)dst = *(const uint4*)h;
}

extern "C" __global__ void init_flags_kernel() {
    int t = threadIdx.x;
    if (t < NCTAS) ((int*)g_flags)[t] = 0;
}

// Grid barrier over one chain's 128 CTAs. Writers must fence before arrival.
__device__ __forceinline__ void gbar(int chain, int lc, int tid, int epoch) {
    __syncthreads();
    if (tid == 0) {
        __threadfence();
        atomicExch(&g_flags[chain][lc], epoch);
    }
    if (tid < CPC) {
        volatile int* vf = &g_flags[chain][tid];
        while (*vf < epoch) __nanosleep(64);
    }
    __syncthreads();
    __threadfence();
}

extern "C" __global__ void __launch_bounds__(NTHREADS, 2)
rnn_kernel(const float* __restrict__ pemb, const float* __restrict__ nemb,
           const float* __restrict__ pb1, const float* __restrict__ pb2,
           const float* __restrict__ nb1, const float* __restrict__ nb2,
           const float* __restrict__ rW) {
    __shared__ float ps[H];              // 8 KB staged input vector
    __shared__ float red[32][2][8];      // 2 KB warp partials

    const int tid   = threadIdx.x;
    const int cta   = blockIdx.x;
    const int chain = cta >> 7;
    const int lc    = cta & (CPC - 1);
    const int c0    = lc * COLS;

    const int jv = tid & 1;              // col octet within 16
    const int it = tid >> 1;             // 0..511 row base
    const int warp = tid >> 5, lane = tid & 31;

    const float* B1  = chain ? nb1  : pb1;
    const float* B2  = chain ? nb2  : pb2;
    const float* EMB = chain ? nemb : pemb;

    // seed p = emb
    if (tid < 4) {
        float4 e = __ldcg((const float4*)(EMB + c0) + tid);
        *((float4*)(&g_p[chain][c0]) + tid) = e;
        __threadfence();
    }

    // prefetch weights for phase 0
    const uint4* wq;
    {
        const __half* wb = g_wh[chain * 4] + (size_t)lc * H * 16;
        wq = (const uint4*)wb;
    }
    uint4 w0 = wq[(size_t)it * 2 + jv];
    uint4 w1 = wq[(size_t)(it + 512) * 2 + jv];
    uint4 w2 = wq[(size_t)(it + 1024) * 2 + jv];
    uint4 w3 = wq[(size_t)(it + 1536) * 2 + jv];

    int epoch = 1;
    gbar(chain, lc, tid, epoch);

    #pragma unroll 1
    for (int ph = 0; ph < NPHASES; ++ph) {
        const int s = ph >> 2, d = (ph >> 1) & 1, l = ph & 1;
        const float* vec = l ? g_t[chain] : g_p[chain];

        // stage input vector
        ps[tid]        = __ldcg(vec + tid);
        ps[tid + 1024] = __ldcg(vec + tid + 1024);
        __syncthreads();

        float a[8] = {0, 0, 0, 0, 0, 0, 0, 0};
        {
            float pv; const __half2* h;
            #define MAC(W, ROW)                                              \
                pv = ps[ROW]; h = (const __half2*)&(W);                      \
                { float2 f = __half22float2(h[0]); a[0] += pv * f.x; a[1] += pv * f.y; } \
                { float2 f = __half22float2(h[1]); a[2] += pv * f.x; a[3] += pv * f.y; } \
                { float2 f = __half22float2(h[2]); a[4] += pv * f.x; a[5] += pv * f.y; } \
                { float2 f = __half22float2(h[3]); a[6] += pv * f.x; a[7] += pv * f.y; }
            MAC(w0, it)
            MAC(w1, it + 512)
            MAC(w2, it + 1024)
            MAC(w3, it + 1536)
            #undef MAC
        }

        // warp reduction among the 16 lanes sharing this jv
        #pragma unroll
        for (int m = 2; m <= 16; m <<= 1) {
            #pragma unroll
            for (int j = 0; j < 8; ++j)
                a[j] += __shfl_xor_sync(0xffffffffu, a[j], m);
        }
        if (lane < 2) {
            #pragma unroll
            for (int j = 0; j < 8; ++j) red[warp][lane][j] = a[j];
        }
        __syncthreads();

        // finalize 16 output columns
        if (tid < 16) {
            const int jj = tid & 7, j2 = tid >> 3;
            float sum = 0.f;
            #pragma unroll
            for (int w = 0; w < 32; ++w) sum += red[w][j2][jj];

            const int col = c0 + tid;
            if (l == 0) {
                float y = silu(sum + B1[d * H + col]);
                g_t[chain][col] = y;
            } else {
                float pold = __ldcg(&g_p[chain][col]);
                float y = pold + silu(sum + B2[d * H + col]);
                g_p[chain][col] = y;
                if (d == 1) g_tab[chain][s][col] = y;
            }
            __threadfence();
        }

        // prefetch next phase's weights BEFORE the barrier (hides latency)
        if (ph + 1 < NPHASES) {
            const int dn = ((ph + 1) >> 1) & 1, ln = (ph + 1) & 1;
            const __half* wb = g_wh[chain * 4 + dn * 2 + ln] + (size_t)lc * H * 16;
            wq = (const uint4*)wb;
            w0 = wq[(size_t)it * 2 + jv];
            w1 = wq[(size_t)(it + 512) * 2 + jv];
            w2 = wq[(size_t)(it + 1024) * 2 + jv];
            w3 = wq[(size_t)(it + 1536) * 2 + jv];
        }

        gbar(chain, lc, tid, ++epoch);
    }

    // Epilogue: project table rows onto rW (CTA lc handles row lc of chain)
    if (lc < STEPS) {
        const float* row = g_tab[chain][lc];
        const float* rw  = rW + chain * H;
        float ssum = __ldcg(row + tid)        * rw[tid]
                   + __ldcg(row + tid + 1024) * rw[tid + 1024];
        ps[tid] = ssum;
        __syncthreads();
        #pragma unroll
        for (int sft = 512; sft > 0; sft >>= 1) {
            if (tid < sft) ps[tid] += ps[tid + sft];
            __syncthreads();
        }
        if (tid == 0) g_proj[chain][lc] = ps[0];
    }
}

extern "C" __global__ void gather_kernel(const int* __restrict__ x,
                                         const float* __restrict__ rb,
                                         float* __restrict__ out) {
    int b = blockIdx.x * blockDim.x + threadIdx.x;
    if (b < NB) {
        int xp = x[2 * b];
        int xn = x[2 * b + 1];
        float z = g_proj[0][xp] + g_proj[1][xn] + rb[0];
        out[b] = 1.0f / (1.0f + __expf(-z));
    }
}

extern "C" void kernel_launch(void* const* d_in, const int* in_sizes, int n_in,
                              void* d_out, int out_size) {
    (void)in_sizes; (void)n_in; (void)out_size;
    const int*   x    = (const int*)d_in[0];
    const float* pemb = (const float*)d_in[1];
    const float* nemb = (const float*)d_in[2];
    const float* pW1  = (const float*)d_in[3];
    const float* pb1  = (const float*)d_in[4];
    const float* pW2  = (const float*)d_in[5];
    const float* pb2  = (const float*)d_in[6];
    const float* nW1  = (const float*)d_in[7];
    const float* nb1  = (const float*)d_in[8];
    const float* nW2  = (const float*)d_in[9];
    const float* nb2  = (const float*)d_in[10];
    const float* rW   = (const float*)d_in[11];
    const float* rb   = (const float*)d_in[12];
    float* out = (float*)d_out;

    convert_kernel<<<8 * 2048 * 256 / 256, 256>>>(pW1, pW2, nW1, nW2);
    init_flags_kernel<<<1, 256>>>();
    rnn_kernel<<<NCTAS, NTHREADS>>>(pemb, nemb, pb1, pb2, nb1, nb2, rW);
    gather_kernel<<<(NB + 255) / 256, 256>>>(x, rb, out);
}

// round 3
// speedup vs baseline: 2.5195x; 1.3848x over previous
#include <cuda_runtime.h>
#include <cuda_fp16.h>

// ============================================================================
// RNN_35244501631277 — GB300 persistent recurrence, round 3
//
// R2 lesson: per-phase 5.8us = 1.5us L2 weight stream + ~4.3us sync latency
// (write -> fence -> flag -> poll -> re-read = 3 L2 round trips).
// This round: barrier-free dataflow. Every state element is an 8-byte
// (epoch, value) word written with ONE st.global.cg.b64; consumers spin on
// the word itself. Value+flag in the same atomic word => no fences, no flag
// array, single L2 hop per phase. p-residual kept in registers (never
// crosses CTAs). Step table epoch-tagged the same way; epochs zeroed per
// launch so graph replays can't alias.
// ============================================================================

#define H          2048
#define STEPS      119
#define NB         16384
#define CPC        128
#define NCTAS      256
#define NTHREADS   1024
#define COLS       16
#define NPHASES    476

typedef unsigned long long ull;

__device__ __half g_wh[8][H * H];        // fp16 weights, CTA-sliced
__device__ ull    g_sp[2][H];            // p-state (epoch|value) pairs
__device__ ull    g_st[2][H];            // t-state pairs
__device__ ull    g_tabp[2][STEPS][H];   // step table pairs
__device__ float  g_proj[2][STEPS];

#define ZERO_WORDS (2 * H + 2 * H + 2 * STEPS * H)   // 495616

__device__ __forceinline__ float silu(float x) {
    return x / (1.0f + __expf(-x));
}

__device__ __forceinline__ float poll_pair(const ull* p, unsigned expep) {
    ull v;
    asm volatile("ld.global.cg.b64 %0, [%1];" : "=l"(v) : "l"(p));
    while ((unsigned)(v >> 32) != expep) {
        __nanosleep(32);
        asm volatile("ld.global.cg.b64 %0, [%1];" : "=l"(v) : "l"(p));
    }
    return __uint_as_float((unsigned)v);
}

__device__ __forceinline__ void push_pair(ull* p, unsigned ep, float val) {
    ull v = ((ull)ep << 32) | (ull)__float_as_uint(val);
    asm volatile("st.global.cg.b64 [%0], %1;" :: "l"(p), "l"(v) : "memory");
}

// Zero all epoch words (fresh dataflow state every launch / graph replay)
extern "C" __global__ void zero_kernel() {
    int i = blockIdx.x * blockDim.x + threadIdx.x;
    if (i < 2 * H)                ((ull*)g_sp)[i] = 0;
    else if (i < 4 * H)           ((ull*)g_st)[i - 2 * H] = 0;
    else if (i < ZERO_WORDS)      ((ull*)g_tabp)[i - 4 * H] = 0;
}

// fp32 -> fp16 into CTA-sliced layout: dst[m][lc*H*16 + row*16 + c]
extern "C" __global__ void convert_kernel(const float* __restrict__ pW1,
                                          const float* __restrict__ pW2,
                                          const float* __restrict__ nW1,
                                          const float* __restrict__ nW2) {
    const int idx = blockIdx.x * blockDim.x + threadIdx.x;
    const int m   = idx >> 19;
    const int rem = idx & ((1 << 19) - 1);
    const int row = rem >> 8;
    const int g   = rem & 255;

    const int chain = m >> 2, d = (m >> 1) & 1, l = m & 1;
    const float* src = (l ? (chain ? nW2 : pW2) : (chain ? nW1 : pW1))
                       + (size_t)d * H * H + (size_t)row * H + g * 8;

    float4 f0 = __ldcs((const float4*)src);
    float4 f1 = __ldcs((const float4*)src + 1);

    __half h[8];
    h[0] = __float2half_rn(f0.x); h[1] = __float2half_rn(f0.y);
    h[2] = __float2half_rn(f0.z); h[3] = __float2half_rn(f0.w);
    h[4] = __float2half_rn(f1.x); h[5] = __float2half_rn(f1.y);
    h[6] = __float2half_rn(f1.z); h[7] = __float2half_rn(f1.w);

    const int lc = g >> 1;
    const int co = (g & 1) * 8;
    __half* dst = &g_wh[m][(size_t)lc * H * 16 + row * 16 + co];
    *(uint4*)dst = *(const uint4*)h;
}

extern "C" __global__ void __launch_bounds__(NTHREADS, 2)
rnn_kernel(const float* __restrict__ pemb, const float* __restrict__ nemb,
           const float* __restrict__ pb1, const float* __restrict__ pb2,
           const float* __restrict__ nb1, const float* __restrict__ nb2,
           const float* __restrict__ rW) {
    __shared__ float ps[H];              // staged input vector (8 KB)
    __shared__ float red[32][2][8];      // warp partials (2 KB)

    const int tid   = threadIdx.x;
    const int cta   = blockIdx.x;
    const int chain = cta >> 7;
    const int lc    = cta & (CPC - 1);
    const int c0    = lc * COLS;

    const int jv   = tid & 1;
    const int it   = tid >> 1;
    const int warp = tid >> 5, lane = tid & 31;

    const float* B1  = chain ? nb1  : pb1;
    const float* B2  = chain ? nb2  : pb2;
    const float* EMB = chain ? nemb : pemb;

    // seed: own 16 p-columns live in a register (tid<16), publish epoch 1
    float pcur = 0.f;
    if (tid < COLS) {
        pcur = __ldcg(EMB + c0 + tid);
        push_pair(&g_sp[chain][c0 + tid], 1u, pcur);
    }

    // prefetch phase-0 weights
    const uint4* wq = (const uint4*)(g_wh[chain * 4] + (size_t)lc * H * 16);
    uint4 w0 = wq[(size_t)it * 2 + jv];
    uint4 w1 = wq[(size_t)(it + 512) * 2 + jv];
    uint4 w2 = wq[(size_t)(it + 1024) * 2 + jv];
    uint4 w3 = wq[(size_t)(it + 1536) * 2 + jv];

    #pragma unroll 1
    for (int ph = 0; ph < NPHASES; ++ph) {
        const int s = ph >> 2, d = (ph >> 1) & 1, l = ph & 1;
        const unsigned ex = (unsigned)(ph >> 1) + 1u;

        // consume input vector (spin on (epoch|value) words, single L2 hop)
        const ull* in = l ? g_st[chain] : g_sp[chain];
        ps[tid]        = poll_pair(in + tid, ex);
        ps[tid + 1024] = poll_pair(in + tid + 1024, ex);
        __syncthreads();

        float a[8] = {0, 0, 0, 0, 0, 0, 0, 0};
        {
            float pv; const __half2* h;
            #define MAC(W, ROW)                                              \
                pv = ps[ROW]; h = (const __half2*)&(W);                      \
                { float2 f = __half22float2(h[0]); a[0] += pv * f.x; a[1] += pv * f.y; } \
                { float2 f = __half22float2(h[1]); a[2] += pv * f.x; a[3] += pv * f.y; } \
                { float2 f = __half22float2(h[2]); a[4] += pv * f.x; a[5] += pv * f.y; } \
                { float2 f = __half22float2(h[3]); a[6] += pv * f.x; a[7] += pv * f.y; }
            MAC(w0, it)
            MAC(w1, it + 512)
            MAC(w2, it + 1024)
            MAC(w3, it + 1536)
            #undef MAC
        }

        // reduce across the 16 row-groups within each warp
        #pragma unroll
        for (int m = 2; m <= 16; m <<= 1) {
            #pragma unroll
            for (int j = 0; j < 8; ++j)
                a[j] += __shfl_xor_sync(0xffffffffu, a[j], m);
        }
        if (lane < 2) {
            #pragma unroll
            for (int j = 0; j < 8; ++j) red[warp][lane][j] = a[j];
        }
        __syncthreads();

        // finalize + publish own 16 output columns
        if (tid < COLS) {
            const int jj = tid & 7, j2 = tid >> 3;
            float sum = 0.f;
            #pragma unroll
            for (int w = 0; w < 32; ++w) sum += red[w][j2][jj];

            const int col = c0 + tid;
            if (l == 0) {
                float y = silu(sum + B1[d * H + col]);
                push_pair(&g_st[chain][col], ex, y);
            } else {
                float y = pcur + silu(sum + B2[d * H + col]);
                pcur = y;
                push_pair(&g_sp[chain][col], ex + 1u, y);
                if (d == 1)
                    push_pair(&g_tabp[chain][s][col], (unsigned)s + 1u, y);
            }
        }

        // prefetch next phase's weights (overlaps the next spin wait)
        if (ph + 1 < NPHASES) {
            const int dn = ((ph + 1) >> 1) & 1, ln = (ph + 1) & 1;
            wq = (const uint4*)(g_wh[chain * 4 + dn * 2 + ln]
                                + (size_t)lc * H * 16);
            w0 = wq[(size_t)it * 2 + jv];
            w1 = wq[(size_t)(it + 512) * 2 + jv];
            w2 = wq[(size_t)(it + 1024) * 2 + jv];
            w3 = wq[(size_t)(it + 1536) * 2 + jv];
        }
    }

    // Epilogue: CTA lc (<119) projects table row lc of its chain onto rW.
    if (lc < STEPS) {
        const ull* row = g_tabp[chain][lc];
        const float* rw = rW + chain * H;
        const unsigned ex = (unsigned)lc + 1u;
        float v0 = poll_pair(row + tid, ex);
        float v1 = poll_pair(row + tid + 1024, ex);
        float ssum = v0 * rw[tid] + v1 * rw[tid + 1024];
        ps[tid] = ssum;
        __syncthreads();
        #pragma unroll
        for (int sft = 512; sft > 0; sft >>= 1) {
            if (tid < sft) ps[tid] += ps[tid + sft];
            __syncthreads();
        }
        if (tid == 0) g_proj[chain][lc] = ps[0];
    }
}

extern "C" __global__ void gather_kernel(const int* __restrict__ x,
                                         const float* __restrict__ rb,
                                         float* __restrict__ out) {
    int b = blockIdx.x * blockDim.x + threadIdx.x;
    if (b < NB) {
        int xp = x[2 * b];
        int xn = x[2 * b + 1];
        float z = g_proj[0][xp] + g_proj[1][xn] + rb[0];
        out[b] = 1.0f / (1.0f + __expf(-z));
    }
}

extern "C" void kernel_launch(void* const* d_in, const int* in_sizes, int n_in,
                              void* d_out, int out_size) {
    (void)in_sizes; (void)n_in; (void)out_size;
    const int*   x    = (const int*)d_in[0];
    const float* pemb = (const float*)d_in[1];
    const float* nemb = (const float*)d_in[2];
    const float* pW1  = (const float*)d_in[3];
    const float* pb1  = (const float*)d_in[4];
    const float* pW2  = (const float*)d_in[5];
    const float* pb2  = (const float*)d_in[6];
    const float* nW1  = (const float*)d_in[7];
    const float* nb1  = (const float*)d_in[8];
    const float* nW2  = (const float*)d_in[9];
    const float* nb2  = (const float*)d_in[10];
    const float* rW   = (const float*)d_in[11];
    const float* rb   = (const float*)d_in[12];
    float* out = (float*)d_out;

    zero_kernel<<<(ZERO_WORDS + 255) / 256, 256>>>();
    convert_kernel<<<8 * 2048 * 256 / 256, 256>>>(pW1, pW2, nW1, nW2);
    rnn_kernel<<<NCTAS, NTHREADS>>>(pemb, nemb, pb1, pb2, nb1, nb2, rW);
    gather_kernel<<<(NB + 255) / 256, 256>>>(x, rb, out);
}

// round 7
// speedup vs baseline: 3.4699x; 1.3772x over previous
#include <cuda_runtime.h>
#include <cuda_fp16.h>

// ============================================================================
// RNN_35244501631277 — GB300 persistent recurrence, round 4 design
// (fourth submit; rounds 4-6 all hit GPU acquisition timeouts).
//
// R3 lesson: per-phase 4.1us vs ~1.6us L2 floor; residual is max-of-128-CTA
// tail latency (SM sharing at occ=2 + per-phase jitter), paid 476 times.
// This design: 64 CTAs/chain x 32 cols, 128 CTAs total -> 1 CTA/SM (no L1
// sharing), max over 64 producers instead of 128, 2x per-thread load ILP.
// Epoch-in-word dataflow, fp16 weights, per-launch epoch zeroing retained.
// ============================================================================

#define H          2048
#define STEPS      119
#define NB         16384
#define CPC        64         // CTAs per chain
#define NCTAS      128
#define NTHREADS   1024
#define COLS       32
#define NPHASES    476

typedef unsigned long long ull;

__device__ __half g_wh[8][H * H];        // fp16 weights, CTA-sliced (32 cols)
__device__ ull    g_sp[2][H];            // p-state (epoch|value) words
__device__ ull    g_st[2][H];            // t-state words
__device__ ull    g_tabp[2][STEPS][H];   // step-table words
__device__ float  g_proj[2][STEPS];

#define ZERO_WORDS (2 * H + 2 * H + 2 * STEPS * H)

__device__ __forceinline__ float silu(float x) {
    return x / (1.0f + __expf(-x));
}

__device__ __forceinline__ float poll_pair(const ull* p, unsigned expep) {
    ull v;
    asm volatile("ld.global.cg.b64 %0, [%1];" : "=l"(v) : "l"(p));
    while ((unsigned)(v >> 32) != expep) {
        __nanosleep(32);
        asm volatile("ld.global.cg.b64 %0, [%1];" : "=l"(v) : "l"(p));
    }
    return __uint_as_float((unsigned)v);
}

__device__ __forceinline__ void push_pair(ull* p, unsigned ep, float val) {
    ull v = ((ull)ep << 32) | (ull)__float_as_uint(val);
    asm volatile("st.global.cg.b64 [%0], %1;" :: "l"(p), "l"(v) : "memory");
}

extern "C" __global__ void zero_kernel() {
    int i = blockIdx.x * blockDim.x + threadIdx.x;
    if (i < 2 * H)           ((ull*)g_sp)[i] = 0;
    else if (i < 4 * H)      ((ull*)g_st)[i - 2 * H] = 0;
    else if (i < ZERO_WORDS) ((ull*)g_tabp)[i - 4 * H] = 0;
}

// fp32 -> fp16, CTA-sliced 32-col layout: dst[m][lc*H*32 + row*32 + co]
extern "C" __global__ void convert_kernel(const float* __restrict__ pW1,
                                          const float* __restrict__ pW2,
                                          const float* __restrict__ nW1,
                                          const float* __restrict__ nW2) {
    const int idx = blockIdx.x * blockDim.x + threadIdx.x;
    const int m   = idx >> 19;
    const int rem = idx & ((1 << 19) - 1);
    const int row = rem >> 8;
    const int g   = rem & 255;            // 8-col group

    const int chain = m >> 2, d = (m >> 1) & 1, l = m & 1;
    const float* src = (l ? (chain ? nW2 : pW2) : (chain ? nW1 : pW1))
                       + (size_t)d * H * H + (size_t)row * H + g * 8;

    float4 f0 = __ldcs((const float4*)src);
    float4 f1 = __ldcs((const float4*)src + 1);

    __half h[8];
    h[0] = __float2half_rn(f0.x); h[1] = __float2half_rn(f0.y);
    h[2] = __float2half_rn(f0.z); h[3] = __float2half_rn(f0.w);
    h[4] = __float2half_rn(f1.x); h[5] = __float2half_rn(f1.y);
    h[6] = __float2half_rn(f1.z); h[7] = __float2half_rn(f1.w);

    const int lc = g >> 2;                // 32-col slice index
    const int co = (g & 3) * 8;
    __half* dst = &g_wh[m][(size_t)lc * H * 32 + (size_t)row * 32 + co];
    *(uint4*)dst = *(const uint4*)h;
}

extern "C" __global__ void __launch_bounds__(NTHREADS, 1)
rnn_kernel(const float* __restrict__ pemb, const float* __restrict__ nemb,
           const float* __restrict__ pb1, const float* __restrict__ pb2,
           const float* __restrict__ nb1, const float* __restrict__ nb2,
           const float* __restrict__ rW) {
    __shared__ float ps[H];              // staged input vector (8 KB)
    __shared__ float red[32][4][8];      // warp partials (4 KB)

    const int tid   = threadIdx.x;
    const int cta   = blockIdx.x;
    const int chain = cta >> 6;
    const int lc    = cta & (CPC - 1);
    const int c0    = lc * COLS;

    const int jv   = tid & 3;            // col octet 0..3 (8 cols each)
    const int it   = tid >> 2;           // 0..255 row base
    const int warp = tid >> 5, lane = tid & 31;

    const float* B1  = chain ? nb1  : pb1;
    const float* B2  = chain ? nb2  : pb2;
    const float* EMB = chain ? nemb : pemb;

    // seed: own 32 p-columns in a register (tid<32), publish epoch 1
    float pcur = 0.f;
    if (tid < COLS) {
        pcur = __ldcg(EMB + c0 + tid);
        push_pair(&g_sp[chain][c0 + tid], 1u, pcur);
    }

    // prefetch phase-0 weights: 8 row-blocks x 8 cols per thread
    const uint4* wq = (const uint4*)(g_wh[chain * 4] + (size_t)lc * H * 32);
    uint4 w[8];
    #pragma unroll
    for (int k = 0; k < 8; ++k)
        w[k] = wq[(size_t)(it + (k << 8)) * 4 + jv];

    #pragma unroll 1
    for (int ph = 0; ph < NPHASES; ++ph) {
        const int s = ph >> 2, d = (ph >> 1) & 1, l = ph & 1;
        const unsigned ex = (unsigned)(ph >> 1) + 1u;

        // consume input vector (spin on epoch|value words)
        const ull* in = l ? g_st[chain] : g_sp[chain];
        ps[tid]        = poll_pair(in + tid, ex);
        ps[tid + 1024] = poll_pair(in + tid + 1024, ex);
        __syncthreads();

        float a[8] = {0, 0, 0, 0, 0, 0, 0, 0};
        #pragma unroll
        for (int k = 0; k < 8; ++k) {
            const float pv = ps[it + (k << 8)];
            const __half2* h = (const __half2*)&w[k];
            { float2 f = __half22float2(h[0]); a[0] += pv * f.x; a[1] += pv * f.y; }
            { float2 f = __half22float2(h[1]); a[2] += pv * f.x; a[3] += pv * f.y; }
            { float2 f = __half22float2(h[2]); a[4] += pv * f.x; a[5] += pv * f.y; }
            { float2 f = __half22float2(h[3]); a[6] += pv * f.x; a[7] += pv * f.y; }
        }

        // prefetch next phase's weights NOW (w[] dead; overlaps reduce/poll)
        if (ph + 1 < NPHASES) {
            const int dn = ((ph + 1) >> 1) & 1, ln = (ph + 1) & 1;
            wq = (const uint4*)(g_wh[chain * 4 + dn * 2 + ln]
                                + (size_t)lc * H * 32);
            #pragma unroll
            for (int k = 0; k < 8; ++k)
                w[k] = wq[(size_t)(it + (k << 8)) * 4 + jv];
        }

        // reduce the 8 it-groups within each warp (lanes differ in bits 2..4)
        #pragma unroll
        for (int m = 4; m <= 16; m <<= 1) {
            #pragma unroll
            for (int j = 0; j < 8; ++j)
                a[j] += __shfl_xor_sync(0xffffffffu, a[j], m);
        }
        if (lane < 4) {
            #pragma unroll
            for (int j = 0; j < 8; ++j) red[warp][lane][j] = a[j];
        }
        __syncthreads();

        // finalize + publish the CTA's 32 output columns
        if (tid < COLS) {
            const int j2 = tid >> 3, jj = tid & 7;
            float sum = 0.f;
            #pragma unroll
            for (int wi = 0; wi < 32; ++wi) sum += red[wi][j2][jj];

            const int col = c0 + tid;
            if (l == 0) {
                float y = silu(sum + B1[d * H + col]);
                push_pair(&g_st[chain][col], ex, y);
            } else {
                float y = pcur + silu(sum + B2[d * H + col]);
                pcur = y;
                push_pair(&g_sp[chain][col], ex + 1u, y);
                if (d == 1)
                    push_pair(&g_tabp[chain][s][col], (unsigned)s + 1u, y);
            }
        }
    }

    // Epilogue: each CTA projects table rows lc and lc+64 of its chain.
    #pragma unroll
    for (int rr = 0; rr < 2; ++rr) {
        const int r = lc + rr * CPC;
        if (r < STEPS) {
            const ull* row = g_tabp[chain][r];
            const float* rw = rW + chain * H;
            const unsigned ex = (unsigned)r + 1u;
            float v0 = poll_pair(row + tid, ex);
            float v1 = poll_pair(row + tid + 1024, ex);
            float ssum = v0 * rw[tid] + v1 * rw[tid + 1024];
            __syncthreads();
            ps[tid] = ssum;
            __syncthreads();
            #pragma unroll
            for (int sft = 512; sft > 0; sft >>= 1) {
                if (tid < sft) ps[tid] += ps[tid + sft];
                __syncthreads();
            }
            if (tid == 0) g_proj[chain][r] = ps[0];
        }
    }
}

extern "C" __global__ void gather_kernel(const int* __restrict__ x,
                                         const float* __restrict__ rb,
                                         float* __restrict__ out) {
    int b = blockIdx.x * blockDim.x + threadIdx.x;
    if (b < NB) {
        int xp = x[2 * b];
        int xn = x[2 * b + 1];
        float z = g_proj[0][xp] + g_proj[1][xn] + rb[0];
        out[b] = 1.0f / (1.0f + __expf(-z));
    }
}

extern "C" void kernel_launch(void* const* d_in, const int* in_sizes, int n_in,
                              void* d_out, int out_size) {
    (void)in_sizes; (void)n_in; (void)out_size;
    const int*   x    = (const int*)d_in[0];
    const float* pemb = (const float*)d_in[1];
    const float* nemb = (const float*)d_in[2];
    const float* pW1  = (const float*)d_in[3];
    const float* pb1  = (const float*)d_in[4];
    const float* pW2  = (const float*)d_in[5];
    const float* pb2  = (const float*)d_in[6];
    const float* nW1  = (const float*)d_in[7];
    const float* nb1  = (const float*)d_in[8];
    const float* nW2  = (const float*)d_in[9];
    const float* nb2  = (const float*)d_in[10];
    const float* rW   = (const float*)d_in[11];
    const float* rb   = (const float*)d_in[12];
    float* out = (float*)d_out;

    zero_kernel<<<(ZERO_WORDS + 255) / 256, 256>>>();
    convert_kernel<<<8 * 2048 * 256 / 256, 256>>>(pW1, pW2, nW1, nW2);
    rnn_kernel<<<NCTAS, NTHREADS>>>(pemb, nemb, pb1, pb2, nb1, nb2, rW);
    gather_kernel<<<(NB + 255) / 256, 256>>>(x, rb, out);
}